// round 5
// baseline (speedup 1.0000x reference)
#include <cuda_runtime.h>
#include <math.h>

#define NB   8
#define CI   64
#define CO   64
#define NCTX 16
#define H    128
#define W    128
#define HW   16384
#define FLEN 576    // CI * 3 * 3

#define TH   8
#define TW   32
#define CCH  8
#define GSTR 10     // floats per pixel-group (8 px + 2 halo)
#define VS   44     // v_s row stride in floats
#define KP   66     // k_s row stride (floats)

// Scratch (allocation-free rule: __device__ globals)
__device__ float g_xmean[NB * CI];
__device__ float g_ker[NB * CO * FLEN];
__device__ float g_v[NB * CI * HW];

typedef unsigned long long u64;

__device__ __forceinline__ u64 fma2(u64 a, u64 b, u64 c) {
    u64 d;
    asm("fma.rn.f32x2 %0, %1, %2, %3;" : "=l"(d) : "l"(a), "l"(b), "l"(c));
    return d;
}
__device__ __forceinline__ u64 pack2(float x, float y) {
    u64 r;
    asm("mov.b64 %0, {%1, %2};" : "=l"(r) : "f"(x), "f"(y));
    return r;
}

// ---------------- kernel 1: per-(b,c) spatial mean ----------------
__global__ void mean_kernel(const float* __restrict__ x) {
    int bc  = blockIdx.x;          // b*CI + c
    int tid = threadIdx.x;         // 256
    const float4* p = (const float4*)(x + (size_t)bc * HW);
    float s = 0.f;
#pragma unroll
    for (int k = 0; k < 16; k++) {
        float4 v = p[tid + k * 256];
        s += (v.x + v.y) + (v.z + v.w);
    }
    __shared__ float red[256];
    red[tid] = s;
    __syncthreads();
    for (int off = 128; off > 0; off >>= 1) {
        if (tid < off) red[tid] += red[tid + off];
        __syncthreads();
    }
    if (tid == 0) g_xmean[bc] = red[0] * (1.f / 16384.f);
}

// ---------------- kernel 2: kernel gen (ctx matvec fused in) ----------------
__global__ void kergen_kernel(const float* __restrict__ ctx_w,
                              const float* __restrict__ ctx_b,
                              const float* __restrict__ kg_w,
                              const float* __restrict__ kg_b,
                              const float* __restrict__ gamma) {
    int bo  = blockIdx.x;          // b*CO + o
    int o   = bo & 63;
    int tid = threadIdx.x;         // 256
    __shared__ float ctx_s[NCTX];
    if (tid < NCTX) {
        int b = bo >> 6;
        float s = ctx_b[tid];
#pragma unroll
        for (int c = 0; c < CI; c++)
            s += ctx_w[tid * CI + c] * g_xmean[b * CI + c];
        ctx_s[tid] = s;
    }
    __syncthreads();

    float vals[3];
    float part = 0.f;
#pragma unroll
    for (int i = 0; i < 3; i++) {
        int f = tid + i * 256;
        vals[i] = 0.f;
        if (f < FLEN) {
            long row = (long)o * FLEN + f;
            const float4* wp = (const float4*)(kg_w + row * 16);
            float s = kg_b[row];
#pragma unroll
            for (int q = 0; q < 4; q++) {
                float4 w4 = wp[q];
                s += w4.x * ctx_s[q * 4 + 0] + w4.y * ctx_s[q * 4 + 1]
                   + w4.z * ctx_s[q * 4 + 2] + w4.w * ctx_s[q * 4 + 3];
            }
            vals[i] = tanhf(s);
            part += vals[i];
        }
    }
    __shared__ float red[256];
    red[tid] = part;
    __syncthreads();
    for (int off = 128; off > 0; off >>= 1) {
        if (tid < off) red[tid] += red[tid + off];
        __syncthreads();
    }
    float lam = 1.f / (1.f + expf(-gamma[o]));
    float sub = lam * (red[0] * (1.f / 576.f));
#pragma unroll
    for (int i = 0; i < 3; i++) {
        int f = tid + i * 256;
        if (f < FLEN) g_ker[(long)bo * FLEN + f] = vals[i] - sub;
    }
}

// ---------------- kernel 3: value projection (1x1 conv, f32x2) ------------
__global__ __launch_bounds__(256, 2)
void vproj_kernel(const float* __restrict__ x,
                  const float* __restrict__ vw) {
    int tid = threadIdx.x;         // 256
    int b   = blockIdx.z;
    int ocg = blockIdx.y;          // 0..3 (16 oc each)
    int p0  = blockIdx.x * 1024 + tid * 4;

    __shared__ float2 w2_s[16][CI];        // duplicated weights, 8 KB
    for (int e = tid; e < 16 * CI; e += 256) {
        int o = e >> 6, c = e & 63;
        float w = vw[(ocg * 16 + o) * CI + c];
        w2_s[o][c] = make_float2(w, w);
    }
    __syncthreads();

    u64 acc[16][2];
#pragma unroll
    for (int o = 0; o < 16; o++) { acc[o][0] = 0ULL; acc[o][1] = 0ULL; }

    const float* xb = x + (size_t)b * CI * HW;
#pragma unroll 2
    for (int c = 0; c < CI; c++) {
        float4 xv = *(const float4*)(xb + (size_t)c * HW + p0);
        u64 x01 = pack2(xv.x, xv.y);
        u64 x23 = pack2(xv.z, xv.w);
#pragma unroll
        for (int o = 0; o < 16; o++) {
            u64 w2 = *(const u64*)&w2_s[o][c];
            acc[o][0] = fma2(w2, x01, acc[o][0]);
            acc[o][1] = fma2(w2, x23, acc[o][1]);
        }
    }
    float* vb = g_v + (size_t)b * CI * HW;
#pragma unroll
    for (int o = 0; o < 16; o++) {
        float2 a  = *(float2*)&acc[o][0];
        float2 c2 = *(float2*)&acc[o][1];
        *(float4*)(vb + (size_t)(ocg * 16 + o) * HW + p0) =
            make_float4(a.x, a.y, c2.x, c2.y);
    }
}

// ---- kernel 4: dynamic 3x3 conv + bias + relu (pixel-paired f32x2) -------
__global__ __launch_bounds__(256, 2)
void conv_kernel(const float* __restrict__ bias, float* __restrict__ out) {
    __shared__ float v_s[CCH][TH + 2][VS];       // plain v, grouped: 14.1 KB
    __shared__ float k_s[CCH * 9][KP];           // transposed kernels: 18.6 KB

    int tid  = threadIdx.x;                      // 256
    int b    = blockIdx.y;
    int tile = blockIdx.x;                       // 64 tiles
    int tx0  = (tile & 3) * TW;
    int ty0  = (tile >> 2) * TH;
    int ocb  = (tid >> 5) * 8;                   // warp -> 8 ocs
    int pg   = tid & 31;
    int g    = pg >> 3;                          // 0..3 pixel group (8 px each)
    int ty   = pg & 7;                           // 0..7 row

    // acc2[o][q]: o = oc within warp's 8, q = pixel pair (px 8g+2q, 8g+2q+1)
    u64 acc2[8][4];
#pragma unroll
    for (int o = 0; o < 8; o++)
#pragma unroll
        for (int q = 0; q < 4; q++) acc2[o][q] = 0ULL;

    const float* vb = g_v + (size_t)b * CI * HW;
    const float* kb = g_ker + (size_t)b * CO * FLEN;

    for (int c0 = 0; c0 < CI; c0 += CCH) {
        __syncthreads();
        // stage v tile: per-group storage, group gg holds input cols
        // [tx0 + 8*gg - 1, tx0 + 8*gg + 8] (10 floats), zero-padded at borders
        for (int e = tid; e < CCH * (TH + 2) * 40; e += 256) {
            int cc  = e / ((TH + 2) * 40);
            int rem = e - cc * ((TH + 2) * 40);
            int ry  = rem / 40;
            int s   = rem - ry * 40;             // 0..39
            int gg  = s / GSTR;
            int j   = s - gg * GSTR;             // 0..9
            int gy  = ty0 + ry - 1;
            int gx  = tx0 + 8 * gg - 1 + j;
            float val = 0.f;
            if (gy >= 0 && gy < H && gx >= 0 && gx < W)
                val = vb[(size_t)(c0 + cc) * HW + gy * W + gx];
            v_s[cc][ry][gg * GSTR + j] = val;
        }
        // stage kernel slice TRANSPOSED: k_s[t][oc], t = cc*9+kh*3+kw
        for (int e = tid; e < CO * CCH * 9; e += 256) {
            int oc = e / (CCH * 9);
            int t  = e - oc * (CCH * 9);
            k_s[t][oc] = kb[(size_t)oc * FLEN + c0 * 9 + t];
        }
        __syncthreads();

#pragma unroll 1
        for (int cc = 0; cc < CCH; cc++) {
#pragma unroll
            for (int kh = 0; kh < 3; kh++) {
                const float* row = &v_s[cc][ty + kh][g * GSTR];
                // aligned pairs (r0,r1),(r2,r3),...,(r8,r9)
                u64 va[5];
#pragma unroll
                for (int q = 0; q < 5; q++)
                    va[q] = *(const u64*)(row + 2 * q);
                // misaligned pairs (r1,r2),(r3,r4),(r5,r6),(r7,r8)
                u64 vm[4];
#pragma unroll
                for (int q = 0; q < 4; q++) {
                    float2 lo = *(float2*)&va[q];
                    float2 hi = *(float2*)&va[q + 1];
                    vm[q] = pack2(lo.y, hi.x);
                }
                const float* krow = &k_s[cc * 9 + kh * 3][0];
#pragma unroll
                for (int o = 0; o < 8; o++) {
                    float w0 = krow[ocb + o];
                    float w1 = krow[KP + ocb + o];
                    float w2 = krow[2 * KP + ocb + o];
                    u64 W0 = pack2(w0, w0);
                    u64 W1 = pack2(w1, w1);
                    u64 W2 = pack2(w2, w2);
#pragma unroll
                    for (int q = 0; q < 4; q++) {
                        acc2[o][q] = fma2(W0, va[q], acc2[o][q]);
                        acc2[o][q] = fma2(W1, vm[q], acc2[o][q]);
                        acc2[o][q] = fma2(W2, va[q + 1], acc2[o][q]);
                    }
                }
            }
        }
    }

    // epilogue: bias + relu, float4 stores (pairs are adjacent pixels)
#pragma unroll
    for (int o = 0; o < 8; o++) {
        float bz = bias[ocb + o];
        float2 p0 = *(float2*)&acc2[o][0];
        float2 p1 = *(float2*)&acc2[o][1];
        float2 p2 = *(float2*)&acc2[o][2];
        float2 p3 = *(float2*)&acc2[o][3];
        float4 v0 = make_float4(fmaxf(p0.x + bz, 0.f), fmaxf(p0.y + bz, 0.f),
                                fmaxf(p1.x + bz, 0.f), fmaxf(p1.y + bz, 0.f));
        float4 v1 = make_float4(fmaxf(p2.x + bz, 0.f), fmaxf(p2.y + bz, 0.f),
                                fmaxf(p3.x + bz, 0.f), fmaxf(p3.y + bz, 0.f));
        size_t base = (((size_t)b * CO + ocb + o) * H + (ty0 + ty)) * W + tx0 + 8 * g;
        *(float4*)(out + base)     = v0;
        *(float4*)(out + base + 4) = v1;
    }
}

extern "C" void kernel_launch(void* const* d_in, const int* in_sizes, int n_in,
                              void* d_out, int out_size) {
    const float* x       = (const float*)d_in[0];
    const float* ctx_w   = (const float*)d_in[1];
    const float* ctx_b   = (const float*)d_in[2];
    const float* kg_w    = (const float*)d_in[3];
    const float* kg_b    = (const float*)d_in[4];
    const float* gamma   = (const float*)d_in[5];
    const float* bias    = (const float*)d_in[6];
    const float* value_w = (const float*)d_in[7];
    float* out = (float*)d_out;

    mean_kernel<<<NB * CI, 256>>>(x);
    kergen_kernel<<<NB * CO, 256>>>(ctx_w, ctx_b, kg_w, kg_b, gamma);
    vproj_kernel<<<dim3(HW / 1024, CI / 16, NB), 256>>>(x, value_w);
    conv_kernel<<<dim3((W / TW) * (H / TH), NB), 256>>>(bias, out);
}

// round 8
// speedup vs baseline: 1.2245x; 1.2245x over previous
#include <cuda_runtime.h>
#include <math.h>

#define NB   8
#define CI   64
#define CO   64
#define NCTX 16
#define H    128
#define W    128
#define HW   16384
#define FLEN 576    // CI * 3 * 3

#define TH   8
#define TW   32
#define CCH  8
#define VS   35     // odd row stride (floats) -> conflict-free strided LDS.32
#define KP   66     // k_s row stride (floats), even -> aligned oc-pair LDS.64

// Scratch (allocation-free rule: __device__ globals)
__device__ float g_xmean[NB * CI];
__device__ float g_ker[NB * CO * FLEN];
__device__ float g_v[NB * CI * HW];

typedef unsigned long long u64;

__device__ __forceinline__ u64 fma2(u64 a, u64 b, u64 c) {
    u64 d;
    asm("fma.rn.f32x2 %0, %1, %2, %3;" : "=l"(d) : "l"(a), "l"(b), "l"(c));
    return d;
}
__device__ __forceinline__ u64 pack2(float x, float y) {
    u64 r;
    asm("mov.b64 %0, {%1, %2};" : "=l"(r) : "f"(x), "f"(y));
    return r;
}

// ---------------- kernel 1: per-(b,c) spatial mean ----------------
__global__ void mean_kernel(const float* __restrict__ x) {
    int bc  = blockIdx.x;          // b*CI + c
    int tid = threadIdx.x;         // 256
    const float4* p = (const float4*)(x + (size_t)bc * HW);
    float s = 0.f;
#pragma unroll
    for (int k = 0; k < 16; k++) {
        float4 v = p[tid + k * 256];
        s += (v.x + v.y) + (v.z + v.w);
    }
    __shared__ float red[256];
    red[tid] = s;
    __syncthreads();
    for (int off = 128; off > 0; off >>= 1) {
        if (tid < off) red[tid] += red[tid + off];
        __syncthreads();
    }
    if (tid == 0) g_xmean[bc] = red[0] * (1.f / 16384.f);
}

// ---------------- kernel 2: kernel gen (ctx matvec fused in) ----------------
__global__ void kergen_kernel(const float* __restrict__ ctx_w,
                              const float* __restrict__ ctx_b,
                              const float* __restrict__ kg_w,
                              const float* __restrict__ kg_b,
                              const float* __restrict__ gamma) {
    int bo  = blockIdx.x;          // b*CO + o
    int o   = bo & 63;
    int tid = threadIdx.x;         // 256
    __shared__ float ctx_s[NCTX];
    if (tid < NCTX) {
        int b = bo >> 6;
        float s = ctx_b[tid];
#pragma unroll
        for (int c = 0; c < CI; c++)
            s += ctx_w[tid * CI + c] * g_xmean[b * CI + c];
        ctx_s[tid] = s;
    }
    __syncthreads();

    float vals[3];
    float part = 0.f;
#pragma unroll
    for (int i = 0; i < 3; i++) {
        int f = tid + i * 256;
        vals[i] = 0.f;
        if (f < FLEN) {
            long row = (long)o * FLEN + f;
            const float4* wp = (const float4*)(kg_w + row * 16);
            float s = kg_b[row];
#pragma unroll
            for (int q = 0; q < 4; q++) {
                float4 w4 = wp[q];
                s += w4.x * ctx_s[q * 4 + 0] + w4.y * ctx_s[q * 4 + 1]
                   + w4.z * ctx_s[q * 4 + 2] + w4.w * ctx_s[q * 4 + 3];
            }
            vals[i] = tanhf(s);
            part += vals[i];
        }
    }
    __shared__ float red[256];
    red[tid] = part;
    __syncthreads();
    for (int off = 128; off > 0; off >>= 1) {
        if (tid < off) red[tid] += red[tid + off];
        __syncthreads();
    }
    float lam = 1.f / (1.f + expf(-gamma[o]));
    float sub = lam * (red[0] * (1.f / 576.f));
#pragma unroll
    for (int i = 0; i < 3; i++) {
        int f = tid + i * 256;
        if (f < FLEN) g_ker[(long)bo * FLEN + f] = vals[i] - sub;
    }
}

// ---------------- kernel 3: value projection (1x1 conv, f32x2) ------------
__global__ __launch_bounds__(256, 2)
void vproj_kernel(const float* __restrict__ x,
                  const float* __restrict__ vw) {
    int tid = threadIdx.x;         // 256
    int b   = blockIdx.z;
    int ocg = blockIdx.y;          // 0..3 (16 oc each)
    int p0  = blockIdx.x * 1024 + tid * 4;

    __shared__ float2 w2_s[16][CI];        // duplicated weights, 8 KB
    for (int e = tid; e < 16 * CI; e += 256) {
        int o = e >> 6, c = e & 63;
        float w = vw[(ocg * 16 + o) * CI + c];
        w2_s[o][c] = make_float2(w, w);
    }
    __syncthreads();

    u64 acc[16][2];
#pragma unroll
    for (int o = 0; o < 16; o++) { acc[o][0] = 0ULL; acc[o][1] = 0ULL; }

    const float* xb = x + (size_t)b * CI * HW;
#pragma unroll 2
    for (int c = 0; c < CI; c++) {
        float4 xv = *(const float4*)(xb + (size_t)c * HW + p0);
        u64 x01 = pack2(xv.x, xv.y);
        u64 x23 = pack2(xv.z, xv.w);
#pragma unroll
        for (int o = 0; o < 16; o++) {
            u64 w2 = *(const u64*)&w2_s[o][c];
            acc[o][0] = fma2(w2, x01, acc[o][0]);
            acc[o][1] = fma2(w2, x23, acc[o][1]);
        }
    }
    float* vb = g_v + (size_t)b * CI * HW;
#pragma unroll
    for (int o = 0; o < 16; o++) {
        float2 a  = *(float2*)&acc[o][0];
        float2 c2 = *(float2*)&acc[o][1];
        *(float4*)(vb + (size_t)(ocg * 16 + o) * HW + p0) =
            make_float4(a.x, a.y, c2.x, c2.y);
    }
}

// ---- kernel 4: dynamic 3x3 conv + bias + relu (oc-paired f32x2,
//      scalar conflict-free v loads + splat packs) ------------------------
__global__ __launch_bounds__(256, 2)
void conv_kernel(const float* __restrict__ bias, float* __restrict__ out) {
    __shared__ float v_s[CCH][TH + 2][VS];       // scalar v: 11.2 KB
    __shared__ float k_s[CCH * 9][KP];           // transposed kernels: 18.6 KB

    int tid  = threadIdx.x;                      // 256
    int b    = blockIdx.y;
    int tile = blockIdx.x;                       // 64 tiles
    int tx0  = (tile & 3) * TW;
    int ty0  = (tile >> 2) * TH;
    int ocb  = (tid >> 5) * 8;                   // warp -> 8 ocs = 4 oc-pairs
    int pg   = tid & 31;
    int ty   = pg >> 2;                          // 0..7 row
    int txb  = (pg & 3) * 8;                     // 0,8,16,24

    // acc2[j][p]: j = oc-pair (oc ocb+2j, ocb+2j+1), p = pixel tx0+txb+p
    u64 acc2[4][8];
#pragma unroll
    for (int j = 0; j < 4; j++)
#pragma unroll
        for (int p = 0; p < 8; p++) acc2[j][p] = 0ULL;

    const float* vb = g_v + (size_t)b * CI * HW;
    const float* kb = g_ker + (size_t)b * CO * FLEN;

    for (int c0 = 0; c0 < CI; c0 += CCH) {
        __syncthreads();
        // stage v tile with halo: row holds cols [tx0-1, tx0+32] at idx 0..33
        for (int e = tid; e < CCH * (TH + 2) * 34; e += 256) {
            int cc  = e / ((TH + 2) * 34);
            int rem = e - cc * ((TH + 2) * 34);
            int ry  = rem / 34;
            int j   = rem - ry * 34;             // 0..33
            int gy  = ty0 + ry - 1;
            int gx  = tx0 + j - 1;
            float val = 0.f;
            if (gy >= 0 && gy < H && gx >= 0 && gx < W)
                val = vb[(size_t)(c0 + cc) * HW + gy * W + gx];
            v_s[cc][ry][j] = val;
        }
        // stage kernel slice TRANSPOSED: k_s[t][oc], t = cc*9+kh*3+kw
        for (int e = tid; e < CO * CCH * 9; e += 256) {
            int oc = e / (CCH * 9);
            int t  = e - oc * (CCH * 9);
            k_s[t][oc] = kb[(size_t)oc * FLEN + c0 * 9 + t];
        }
        __syncthreads();

#pragma unroll 1
        for (int cc = 0; cc < CCH; cc++) {
#pragma unroll
            for (int kh = 0; kh < 3; kh++) {
                // 10 scalar conflict-free loads, splat into f32x2
                const float* row = &v_s[cc][ty + kh][txb];
                u64 rs[10];
#pragma unroll
                for (int i = 0; i < 10; i++) {
                    float r = row[i];
                    rs[i] = pack2(r, r);
                }
                // oc-pair weights: aligned broadcast LDS.64, zero ALU
                u64 w2[4][3];
#pragma unroll
                for (int j = 0; j < 4; j++)
#pragma unroll
                    for (int kw = 0; kw < 3; kw++)
                        w2[j][kw] = *(const u64*)&k_s[cc * 9 + kh * 3 + kw][ocb + 2 * j];
#pragma unroll
                for (int j = 0; j < 4; j++)
#pragma unroll
                    for (int kw = 0; kw < 3; kw++)
#pragma unroll
                        for (int p = 0; p < 8; p++)
                            acc2[j][p] = fma2(w2[j][kw], rs[p + kw], acc2[j][p]);
            }
        }
    }

    // epilogue: unpack oc-pairs, bias + relu, float4 stores
#pragma unroll
    for (int j = 0; j < 4; j++) {
        float blo = bias[ocb + 2 * j];
        float bhi = bias[ocb + 2 * j + 1];
        float lo[8], hi[8];
#pragma unroll
        for (int p = 0; p < 8; p++) {
            float2 v = *(float2*)&acc2[j][p];
            lo[p] = fmaxf(v.x + blo, 0.f);
            hi[p] = fmaxf(v.y + bhi, 0.f);
        }
        size_t base_lo = (((size_t)b * CO + ocb + 2 * j) * H + (ty0 + ty)) * W + tx0 + txb;
        size_t base_hi = base_lo + (size_t)H * W;
        *(float4*)(out + base_lo)     = make_float4(lo[0], lo[1], lo[2], lo[3]);
        *(float4*)(out + base_lo + 4) = make_float4(lo[4], lo[5], lo[6], lo[7]);
        *(float4*)(out + base_hi)     = make_float4(hi[0], hi[1], hi[2], hi[3]);
        *(float4*)(out + base_hi + 4) = make_float4(hi[4], hi[5], hi[6], hi[7]);
    }
}

extern "C" void kernel_launch(void* const* d_in, const int* in_sizes, int n_in,
                              void* d_out, int out_size) {
    const float* x       = (const float*)d_in[0];
    const float* ctx_w   = (const float*)d_in[1];
    const float* ctx_b   = (const float*)d_in[2];
    const float* kg_w    = (const float*)d_in[3];
    const float* kg_b    = (const float*)d_in[4];
    const float* gamma   = (const float*)d_in[5];
    const float* bias    = (const float*)d_in[6];
    const float* value_w = (const float*)d_in[7];
    float* out = (float*)d_out;

    mean_kernel<<<NB * CI, 256>>>(x);
    kergen_kernel<<<NB * CO, 256>>>(ctx_w, ctx_b, kg_w, kg_b, gamma);
    vproj_kernel<<<dim3(HW / 1024, CI / 16, NB), 256>>>(x, value_w);
    conv_kernel<<<dim3((W / TW) * (H / TH), NB), 256>>>(bias, out);
}